// round 2
// baseline (speedup 1.0000x reference)
#include <cuda_runtime.h>
#include <math_constants.h>

// Batched nearest-neighbor argmin + gather (HBM-streaming).
//   y:      [B, 2] f32, Y_surf: [B, 2, G] f32, U_grid: [2, G] f32, out: [B, 2] f32
//   out[b,:] = U_grid[:, argmin_g ||Y_surf[b,:,g] - y[b,:]||^2]
//
// Warp-per-sample: 8 warps/block, each warp streams its sample's 2xG rows
// with x4-unrolled float4 __ldcs loads (8 independent 128b loads in flight
// per lane) and a single warp-shuffle argmin reduction (first-index ties).

#define NT 256
#define WPB (NT / 32)

__device__ __forceinline__ void upd(float d, int g, float& best, int& bidx) {
    if (d < best) { best = d; bidx = g; }  // strict <: earliest g wins in-thread
}

__device__ __forceinline__ void proc4(float4 a, float4 c, int g,
                                      float y0, float y1,
                                      float& best, int& bidx) {
    float dx, dz, d;
    dx = a.x - y0; dz = c.x - y1; d = dx * dx + dz * dz; upd(d, g + 0, best, bidx);
    dx = a.y - y0; dz = c.y - y1; d = dx * dx + dz * dz; upd(d, g + 1, best, bidx);
    dx = a.z - y0; dz = c.z - y1; d = dx * dx + dz * dz; upd(d, g + 2, best, bidx);
    dx = a.w - y0; dz = c.w - y1; d = dx * dx + dz * dz; upd(d, g + 3, best, bidx);
}

__global__ __launch_bounds__(NT)
void lqr_argmin_warp_kernel(const float* __restrict__ y,
                            const float* __restrict__ Ys,
                            const float* __restrict__ Ug,
                            float* __restrict__ out,
                            int B, int G) {
    const int lane = threadIdx.x & 31;
    const int b = blockIdx.x * WPB + (threadIdx.x >> 5);
    if (b >= B) return;

    const float y0 = __ldg(&y[2 * b + 0]);
    const float y1 = __ldg(&y[2 * b + 1]);

    const float4* __restrict__ v0 =
        reinterpret_cast<const float4*>(Ys + (size_t)b * 2 * G);
    const float4* __restrict__ v1 = v0 + (G >> 2);
    const int n4 = G >> 2;  // G % 4 == 0 (G = 2500)

    float best = CUDART_INF_F;
    int   bidx = 0;

    int i = lane;
    // x4 unroll: front-batch 8 independent 128-bit streaming loads.
    for (; i + 96 < n4; i += 128) {
        float4 a0 = __ldcs(v0 + i);
        float4 a1 = __ldcs(v0 + i + 32);
        float4 a2 = __ldcs(v0 + i + 64);
        float4 a3 = __ldcs(v0 + i + 96);
        float4 c0 = __ldcs(v1 + i);
        float4 c1 = __ldcs(v1 + i + 32);
        float4 c2 = __ldcs(v1 + i + 64);
        float4 c3 = __ldcs(v1 + i + 96);
        proc4(a0, c0, (i)       << 2, y0, y1, best, bidx);
        proc4(a1, c1, (i + 32)  << 2, y0, y1, best, bidx);
        proc4(a2, c2, (i + 64)  << 2, y0, y1, best, bidx);
        proc4(a3, c3, (i + 96)  << 2, y0, y1, best, bidx);
    }
    for (; i < n4; i += 32) {
        float4 a = __ldcs(v0 + i);
        float4 c = __ldcs(v1 + i);
        proc4(a, c, i << 2, y0, y1, best, bidx);
    }

    // Warp argmin reduction: min d2, tie -> min idx (jnp.argmin first-min).
    #pragma unroll
    for (int off = 16; off > 0; off >>= 1) {
        float ob = __shfl_down_sync(0xffffffffu, best, off);
        int   oi = __shfl_down_sync(0xffffffffu, bidx, off);
        if (ob < best || (ob == best && oi < bidx)) { best = ob; bidx = oi; }
    }

    if (lane == 0) {
        out[2 * b + 0] = __ldg(&Ug[bidx]);
        out[2 * b + 1] = __ldg(&Ug[(size_t)G + bidx]);
    }
}

extern "C" void kernel_launch(void* const* d_in, const int* in_sizes, int n_in,
                              void* d_out, int out_size) {
    const float* y  = (const float*)d_in[0];   // [B, 2]
    const float* Ys = (const float*)d_in[1];   // [B, 2, G]
    const float* Ug = (const float*)d_in[2];   // [2, G]
    float* out = (float*)d_out;                // [B, 2]

    const int B = in_sizes[0] / 2;
    const int G = in_sizes[2] / 2;

    const int blocks = (B + WPB - 1) / WPB;
    lqr_argmin_warp_kernel<<<blocks, NT>>>(y, Ys, Ug, out, B, G);
}

// round 3
// speedup vs baseline: 1.0807x; 1.0807x over previous
#include <cuda_runtime.h>
#include <math_constants.h>

// Batched nearest-neighbor argmin + gather (HBM-streaming).
//   y: [B,2] f32, Y_surf: [B,2,G] f32, U_grid: [2,G] f32, out: [B,2] f32
//   out[b,:] = U_grid[:, argmin_g ||Y_surf[b,:,g] - y[b,:]||^2]
//
// Block-per-sample (128 thr), float4 loads, x2 unroll (4 independent LDG.128
// front-batched), and 4 INDEPENDENT argmin accumulators per thread (one per
// float4 lane) so the FSETP/@SEL update chain is depth-1 per group instead
// of depth-4. Merge with (d2, idx) lexicographic tie-break = jnp.argmin.

#define NT 128

struct Acc { float d[4]; int g[4]; };

__device__ __forceinline__ void proc4(const float4& a, const float4& c, int g,
                                      float y0, float y1, Acc& acc) {
    float dx, dz, d;
    dx = a.x - y0; dz = c.x - y1; d = dx * dx + dz * dz;
    if (d < acc.d[0]) { acc.d[0] = d; acc.g[0] = g + 0; }
    dx = a.y - y0; dz = c.y - y1; d = dx * dx + dz * dz;
    if (d < acc.d[1]) { acc.d[1] = d; acc.g[1] = g + 1; }
    dx = a.z - y0; dz = c.z - y1; d = dx * dx + dz * dz;
    if (d < acc.d[2]) { acc.d[2] = d; acc.g[2] = g + 2; }
    dx = a.w - y0; dz = c.w - y1; d = dx * dx + dz * dz;
    if (d < acc.d[3]) { acc.d[3] = d; acc.g[3] = g + 3; }
}

__global__ __launch_bounds__(NT, 8)
void lqr_argmin_kernel(const float* __restrict__ y,
                       const float* __restrict__ Ys,
                       const float* __restrict__ Ug,
                       float* __restrict__ out,
                       int G) {
    const int b   = blockIdx.x;
    const int tid = threadIdx.x;

    const float y0 = y[2 * b + 0];
    const float y1 = y[2 * b + 1];

    const float4* __restrict__ v0 =
        reinterpret_cast<const float4*>(Ys + (size_t)b * 2 * G);
    const float4* __restrict__ v1 = v0 + (G >> 2);
    const int n4 = G >> 2;  // G % 4 == 0 (G = 2500)

    Acc acc;
    #pragma unroll
    for (int k = 0; k < 4; k++) { acc.d[k] = CUDART_INF_F; acc.g[k] = 0; }

    int i = tid;
    // x2 unroll: 4 independent 128-bit loads in flight per thread.
    for (; i + NT < n4; i += 2 * NT) {
        float4 a0 = v0[i];
        float4 a1 = v0[i + NT];
        float4 c0 = v1[i];
        float4 c1 = v1[i + NT];
        proc4(a0, c0, i << 2,        y0, y1, acc);
        proc4(a1, c1, (i + NT) << 2, y0, y1, acc);
    }
    if (i < n4) {
        float4 a = v0[i];
        float4 c = v1[i];
        proc4(a, c, i << 2, y0, y1, acc);
    }

    // Merge the 4 accumulators: min d2, tie -> min idx.
    float best = acc.d[0];
    int   bidx = acc.g[0];
    #pragma unroll
    for (int k = 1; k < 4; k++) {
        if (acc.d[k] < best || (acc.d[k] == best && acc.g[k] < bidx)) {
            best = acc.d[k]; bidx = acc.g[k];
        }
    }

    // Warp reduction (first-min tie-break).
    #pragma unroll
    for (int off = 16; off > 0; off >>= 1) {
        float ob = __shfl_down_sync(0xffffffffu, best, off);
        int   oi = __shfl_down_sync(0xffffffffu, bidx, off);
        if (ob < best || (ob == best && oi < bidx)) { best = ob; bidx = oi; }
    }

    __shared__ float sb[NT / 32];
    __shared__ int   si[NT / 32];
    const int w = tid >> 5;
    if ((tid & 31) == 0) { sb[w] = best; si[w] = bidx; }
    __syncthreads();

    if (w == 0) {
        const int nw = NT / 32;
        best = (tid < nw) ? sb[tid] : CUDART_INF_F;
        bidx = (tid < nw) ? si[tid] : 0x7fffffff;
        #pragma unroll
        for (int off = 16; off > 0; off >>= 1) {
            float ob = __shfl_down_sync(0xffffffffu, best, off);
            int   oi = __shfl_down_sync(0xffffffffu, bidx, off);
            if (ob < best || (ob == best && oi < bidx)) { best = ob; bidx = oi; }
        }
        if (tid == 0) {
            out[2 * b + 0] = Ug[bidx];
            out[2 * b + 1] = Ug[(size_t)G + bidx];
        }
    }
}

extern "C" void kernel_launch(void* const* d_in, const int* in_sizes, int n_in,
                              void* d_out, int out_size) {
    const float* y  = (const float*)d_in[0];   // [B, 2]
    const float* Ys = (const float*)d_in[1];   // [B, 2, G]
    const float* Ug = (const float*)d_in[2];   // [2, G]
    float* out = (float*)d_out;                // [B, 2]

    const int B = in_sizes[0] / 2;
    const int G = in_sizes[2] / 2;

    lqr_argmin_kernel<<<B, NT>>>(y, Ys, Ug, out, G);
}